// round 3
// baseline (speedup 1.0000x reference)
#include <cuda_runtime.h>
#include <math.h>

#define H 2048
#define H4 512          // float4 per row
#define NT 128

// Scratch (device globals; zero-initialized at module load)
__device__ __align__(16) float g_h[2 * H];        // h outputs of layers 0,1
__device__ __align__(16) float g_pg[2][4 * H];    // partial gates for layers 1,2
__device__ int g_cnt0, g_cntA, g_cntB, g_cnt1, g_done;

__device__ __forceinline__ float sigmoidf_(float x) { return 1.0f / (1.0f + expf(-x)); }

__device__ __forceinline__ float warp_red(float v) {
    #pragma unroll
    for (int o = 16; o > 0; o >>= 1) v += __shfl_xor_sync(0xffffffffu, v, o);
    return v;
}
__device__ __forceinline__ float d4(float4 a, float4 b) {
    return a.x * b.x + a.y * b.y + a.z * b.z + a.w * b.w;
}

// Grid layout (block id order == dependency order; B300 dispatches in id order):
//  [0,2048)      layer0 full:   Whh0 . hid0 + epilogue -> g_h[0..H), cnt0
//  [2048,4096)   Whh1 partial:  Whh1 . hid1 + biases   -> g_pg[0], cntA
//  [4096,6144)   Whh2 partial:  Whh2 . hid2 + biases   -> g_pg[1], cntB
//  [6144,8192)   Wih1 finish:   stage Wih1->smem, spin(cnt0,cntA), dot, epi -> g_h[H..2H), cnt1
//  [8192,10240)  Wih2 finish:   stage Wih2->smem, spin(cnt1,cntB), dot, epi + y proj
__global__ void __launch_bounds__(NT, 6) k_fused(
    const float* __restrict__ x,
    const float* __restrict__ hid,   // [3,H]
    const float* __restrict__ cell,  // [3,H]
    const float* __restrict__ Wih0,  // [4H,1]
    const float* __restrict__ Whh0,
    const float* __restrict__ bih0, const float* __restrict__ bhh0,
    const float* __restrict__ Wih1,
    const float* __restrict__ Whh1,
    const float* __restrict__ bih1, const float* __restrict__ bhh1,
    const float* __restrict__ Wih2,
    const float* __restrict__ Whh2,
    const float* __restrict__ bih2, const float* __restrict__ bhh2,
    const float* __restrict__ Wout,
    const float* __restrict__ bout,
    float* __restrict__ out)
{
    __shared__ float4 sW[4 * H4];       // 32 KB staging (finish groups only)
    __shared__ float  smred[4][4];

    const int b = blockIdx.x;
    const int t = threadIdx.x;
    const int grp = b >> 11;
    const int j = b & (H - 1);

    float s[4] = {0.f, 0.f, 0.f, 0.f};

    if (grp < 3) {
        // ---- pure streaming matvec against provided hidden state ----
        const float* W = (grp == 0) ? Whh0 : ((grp == 1) ? Whh1 : Whh2);
        const float4* h4 = reinterpret_cast<const float4*>(hid + grp * H);
        float4 hv[4];
        #pragma unroll
        for (int k = 0; k < 4; k++) hv[k] = h4[t + NT * k];
        #pragma unroll
        for (int g = 0; g < 4; g++) {
            const float4* row = reinterpret_cast<const float4*>(W) + (size_t)(g * H + j) * H4;
            #pragma unroll
            for (int k = 0; k < 4; k++) {
                float4 a = __ldcs(row + t + NT * k);
                s[g] += d4(a, hv[k]);
            }
        }
    } else {
        // ---- finish groups: stage weights to smem FIRST (overlaps producers), then spin ----
        const int layer = grp - 2;                  // 1 or 2
        const float* W = (layer == 1) ? Wih1 : Wih2;
        #pragma unroll
        for (int g = 0; g < 4; g++) {
            const float4* row = reinterpret_cast<const float4*>(W) + (size_t)(g * H + j) * H4;
            #pragma unroll
            for (int k = 0; k < 4; k++)
                sW[g * H4 + t + NT * k] = __ldcs(row + t + NT * k);
        }
        if (t == 0) {
            volatile int* c1 = (layer == 1) ? &g_cnt0 : &g_cnt1;
            volatile int* c2 = (layer == 1) ? &g_cntA : &g_cntB;
            while (*c1 < H || *c2 < H) __nanosleep(64);
        }
        __syncthreads();
        __threadfence();
        const float4* h4 = reinterpret_cast<const float4*>(g_h + (layer - 1) * H);
        float4 hv[4];
        #pragma unroll
        for (int k = 0; k < 4; k++) hv[k] = __ldcg(h4 + t + NT * k);
        #pragma unroll
        for (int g = 0; g < 4; g++) {
            #pragma unroll
            for (int k = 0; k < 4; k++)
                s[g] += d4(sW[g * H4 + t + NT * k], hv[k]);
        }
    }

    // ---- block reduce (4 warps) ----
    const int lane = t & 31, w = t >> 5;
    #pragma unroll
    for (int g = 0; g < 4; g++) s[g] = warp_red(s[g]);
    if (lane == 0) {
        #pragma unroll
        for (int g = 0; g < 4; g++) smred[w][g] = s[g];
    }
    __syncthreads();
    if (t != 0) return;

    float tot[4];
    #pragma unroll
    for (int g = 0; g < 4; g++)
        tot[g] = smred[0][g] + smred[1][g] + smred[2][g] + smred[3][g];

    if (grp == 0) {
        if (b == 0) out[0] = bout[0];
        const float xv = x[0];
        float gate[4];
        #pragma unroll
        for (int g = 0; g < 4; g++) {
            int r = g * H + j;
            gate[g] = tot[g] + xv * Wih0[r] + bih0[r] + bhh0[r];
        }
        float c2 = sigmoidf_(gate[1]) * cell[j] + sigmoidf_(gate[0]) * tanhf(gate[2]);
        float h2 = sigmoidf_(gate[3]) * tanhf(c2);
        g_h[j] = h2;
        out[1 + j] = h2;
        out[1 + 3 * H + j] = c2;
        __threadfence();
        atomicAdd(&g_cnt0, 1);
    } else if (grp == 1 || grp == 2) {
        const float* bi = (grp == 1) ? bih1 : bih2;
        const float* bb = (grp == 1) ? bhh1 : bhh2;
        float* pg = g_pg[grp - 1];
        #pragma unroll
        for (int g = 0; g < 4; g++) {
            int r = g * H + j;
            pg[r] = tot[g] + bi[r] + bb[r];
        }
        __threadfence();
        atomicAdd((grp == 1) ? &g_cntA : &g_cntB, 1);
    } else {
        const int layer = grp - 2;  // 1 or 2
        const float* pg = g_pg[layer - 1];
        float gate[4];
        #pragma unroll
        for (int g = 0; g < 4; g++) gate[g] = tot[g] + __ldcg(&pg[g * H + j]);
        float c2 = sigmoidf_(gate[1]) * cell[layer * H + j] + sigmoidf_(gate[0]) * tanhf(gate[2]);
        float h2 = sigmoidf_(gate[3]) * tanhf(c2);
        out[1 + layer * H + j] = h2;
        out[1 + 3 * H + layer * H + j] = c2;
        if (layer == 1) {
            g_h[H + j] = h2;
            __threadfence();
            atomicAdd(&g_cnt1, 1);
        } else {
            atomicAdd(&out[0], h2 * __ldg(&Wout[j]));
            // last Wih2 block resets sync state for the next graph replay
            int v = atomicAdd(&g_done, 1);
            if (v == H - 1) {
                g_cnt0 = 0; g_cntA = 0; g_cntB = 0; g_cnt1 = 0; g_done = 0;
            }
        }
    }
}

extern "C" void kernel_launch(void* const* d_in, const int* in_sizes, int n_in,
                              void* d_out, int out_size) {
    const float* x    = (const float*)d_in[0];
    const float* hid  = (const float*)d_in[1];
    const float* cell = (const float*)d_in[2];
    const float* Wih0 = (const float*)d_in[3];
    const float* Whh0 = (const float*)d_in[4];
    const float* bih0 = (const float*)d_in[5];
    const float* bhh0 = (const float*)d_in[6];
    const float* Wih1 = (const float*)d_in[7];
    const float* Whh1 = (const float*)d_in[8];
    const float* bih1 = (const float*)d_in[9];
    const float* bhh1 = (const float*)d_in[10];
    const float* Wih2 = (const float*)d_in[11];
    const float* Whh2 = (const float*)d_in[12];
    const float* bih2 = (const float*)d_in[13];
    const float* bhh2 = (const float*)d_in[14];
    const float* Wout = (const float*)d_in[15];
    const float* bout = (const float*)d_in[16];
    float* out = (float*)d_out;

    k_fused<<<5 * H, NT>>>(x, hid, cell, Wih0,
                           Whh0, bih0, bhh0,
                           Wih1, Whh1, bih1, bhh1,
                           Wih2, Whh2, bih2, bhh2,
                           Wout, bout, out);
}

// round 4
// speedup vs baseline: 1.8168x; 1.8168x over previous
#include <cuda_runtime.h>
#include <math.h>

#define H 2048
#define H4 512
#define FOURH 8192
#define NT 256   // threads per block

// Scratch — h outputs per layer + partial gates for layers 1,2
__device__ __align__(16) float g_h[3 * H];
__device__ __align__(16) float g_pg[2 * FOURH];

__device__ __forceinline__ float sigmoidf_(float x) { return 1.0f / (1.0f + expf(-x)); }

__device__ __forceinline__ float warp_red(float v) {
    #pragma unroll
    for (int o = 16; o > 0; o >>= 1) v += __shfl_xor_sync(0xffffffffu, v, o);
    return v;
}
__device__ __forceinline__ float d4(float4 a, float4 b) {
    return a.x * b.x + a.y * b.y + a.z * b.z + a.w * b.w;
}

// 4 dot products: rows {j, j+H, j+2H, j+3H} of W [4H x H] vs h [H].
// All 8 W loads issued back-to-back into distinct registers BEFORE any FMA,
// so the memory system sees 8 outstanding LDG.128 per thread.
__device__ __forceinline__ void dot4(const float* __restrict__ W, int j,
                                     const float* __restrict__ h, float s[4]) {
    const int t = threadIdx.x;
    const float4* h4 = reinterpret_cast<const float4*>(h);
    const float4* r0 = reinterpret_cast<const float4*>(W) + (size_t)(0 * H + j) * H4;
    const float4* r1 = reinterpret_cast<const float4*>(W) + (size_t)(1 * H + j) * H4;
    const float4* r2 = reinterpret_cast<const float4*>(W) + (size_t)(2 * H + j) * H4;
    const float4* r3 = reinterpret_cast<const float4*>(W) + (size_t)(3 * H + j) * H4;

    float4 a0 = __ldcs(r0 + t);
    float4 a1 = __ldcs(r1 + t);
    float4 a2 = __ldcs(r2 + t);
    float4 a3 = __ldcs(r3 + t);
    float4 b0 = __ldcs(r0 + t + NT);
    float4 b1 = __ldcs(r1 + t + NT);
    float4 b2 = __ldcs(r2 + t + NT);
    float4 b3 = __ldcs(r3 + t + NT);
    float4 hv0 = __ldg(h4 + t);
    float4 hv1 = __ldg(h4 + t + NT);

    s[0] = d4(a0, hv0) + d4(b0, hv1);
    s[1] = d4(a1, hv0) + d4(b1, hv1);
    s[2] = d4(a2, hv0) + d4(b2, hv1);
    s[3] = d4(a3, hv0) + d4(b3, hv1);
}

__device__ __forceinline__ void reduce4(float s[4], float tot[4]) {
    __shared__ float sm[NT / 32][4];
    const int lane = threadIdx.x & 31;
    const int w = threadIdx.x >> 5;
    #pragma unroll
    for (int g = 0; g < 4; g++) s[g] = warp_red(s[g]);
    if (lane == 0) {
        #pragma unroll
        for (int g = 0; g < 4; g++) sm[w][g] = s[g];
    }
    __syncthreads();
    if (threadIdx.x == 0) {
        #pragma unroll
        for (int g = 0; g < 4; g++) {
            float v = 0.0f;
            #pragma unroll
            for (int ww = 0; ww < NT / 32; ww++) v += sm[ww][g];
            tot[g] = v;
        }
    }
}

// Stage 1: [0,2048) layer0 full; [2048,4096) Whh1 partial; [4096,6144) Whh2 partial.
__global__ void __launch_bounds__(NT) k_stage1(
    const float* __restrict__ x,
    const float* __restrict__ hid,
    const float* __restrict__ cell,
    const float* __restrict__ Wih0,
    const float* __restrict__ Whh0,
    const float* __restrict__ bih0, const float* __restrict__ bhh0,
    const float* __restrict__ Whh1,
    const float* __restrict__ bih1, const float* __restrict__ bhh1,
    const float* __restrict__ Whh2,
    const float* __restrict__ bih2, const float* __restrict__ bhh2,
    const float* __restrict__ bout,
    float* __restrict__ out)
{
    const int b = blockIdx.x;
    const int layer = b >> 11;
    const int j = b & (H - 1);

    if (b == 0 && threadIdx.x == 32) out[0] = bout[0];

    const float* W = (layer == 0) ? Whh0 : ((layer == 1) ? Whh1 : Whh2);
    const float* h = hid + layer * H;

    float s[4];
    dot4(W, j, h, s);
    float tot[4];
    reduce4(s, tot);

    if (threadIdx.x == 0) {
        if (layer == 0) {
            const float xv = x[0];
            float gate[4];
            #pragma unroll
            for (int g = 0; g < 4; g++) {
                int r = g * H + j;
                gate[g] = tot[g] + xv * Wih0[r] + bih0[r] + bhh0[r];
            }
            float c2 = sigmoidf_(gate[1]) * cell[j] + sigmoidf_(gate[0]) * tanhf(gate[2]);
            float h2 = sigmoidf_(gate[3]) * tanhf(c2);
            g_h[j] = h2;
            out[1 + j] = h2;
            out[1 + 3 * H + j] = c2;
        } else {
            const float* bi = (layer == 1) ? bih1 : bih2;
            const float* bb = (layer == 1) ? bhh1 : bhh2;
            float* pg = g_pg + (layer - 1) * FOURH;
            #pragma unroll
            for (int g = 0; g < 4; g++) {
                int r = g * H + j;
                pg[r] = tot[g] + bi[r] + bb[r];
            }
        }
    }
}

// Finish layer (1 or 2): gates = pg + Wih * h_prev, then epilogue.
// Layer 2 also accumulates y = sum h2[j]*Wout[j] into out[0] (seeded with bout).
__global__ void __launch_bounds__(NT) k_finish(
    const float* __restrict__ Wih,
    const float* __restrict__ cell,
    const float* __restrict__ Wout,
    int layer,
    float* __restrict__ out)
{
    const int j = blockIdx.x;
    const float* hin = g_h + (layer - 1) * H;

    float s[4];
    dot4(Wih, j, hin, s);
    float tot[4];
    reduce4(s, tot);

    if (threadIdx.x == 0) {
        const float* pg = g_pg + (layer - 1) * FOURH;
        float gate[4];
        #pragma unroll
        for (int g = 0; g < 4; g++) gate[g] = tot[g] + pg[g * H + j];
        float c2 = sigmoidf_(gate[1]) * cell[layer * H + j] + sigmoidf_(gate[0]) * tanhf(gate[2]);
        float h2 = sigmoidf_(gate[3]) * tanhf(c2);
        g_h[layer * H + j] = h2;
        out[1 + layer * H + j] = h2;
        out[1 + 3 * H + layer * H + j] = c2;
        if (layer == 2) {
            atomicAdd(&out[0], h2 * __ldg(&Wout[j]));
        }
    }
}

extern "C" void kernel_launch(void* const* d_in, const int* in_sizes, int n_in,
                              void* d_out, int out_size) {
    const float* x    = (const float*)d_in[0];
    const float* hid  = (const float*)d_in[1];
    const float* cell = (const float*)d_in[2];
    const float* Wih0 = (const float*)d_in[3];
    const float* Whh0 = (const float*)d_in[4];
    const float* bih0 = (const float*)d_in[5];
    const float* bhh0 = (const float*)d_in[6];
    const float* Wih1 = (const float*)d_in[7];
    const float* Whh1 = (const float*)d_in[8];
    const float* bih1 = (const float*)d_in[9];
    const float* bhh1 = (const float*)d_in[10];
    const float* Wih2 = (const float*)d_in[11];
    const float* Whh2 = (const float*)d_in[12];
    const float* bih2 = (const float*)d_in[13];
    const float* bhh2 = (const float*)d_in[14];
    const float* Wout = (const float*)d_in[15];
    const float* bout = (const float*)d_in[16];
    float* out = (float*)d_out;

    k_stage1<<<3 * H, NT>>>(x, hid, cell, Wih0,
                            Whh0, bih0, bhh0,
                            Whh1, bih1, bhh1,
                            Whh2, bih2, bhh2, bout, out);
    k_finish<<<H, NT>>>(Wih1, cell, Wout, 1, out);
    k_finish<<<H, NT>>>(Wih2, cell, Wout, 2, out);
}